// round 13
// baseline (speedup 1.0000x reference)
#include <cuda_runtime.h>
#include <cuda_bf16.h>

// Downsampler: depthwise 4x4 conv, stride 4, VALID -> non-overlapping weighted
// 4x4 block reduction. Pure streaming: 512MB compulsory read, 8MB write.
//
// FINAL: OPT=2, flat grid, dense-per-instruction loads. Each warp owns 64
// consecutive output pixels; lane handles pixels (lane, lane+32), so every
// LDG.E.128 is 512B contiguous across the warp (full sectors, 4 L1 lines).
// MLP_p1=8, 32 regs, occ ~84%, dense STG.32 stores.
//
// Convergence evidence (8 benches):
//  - DRAM active 85-87.3% on exactly-compulsory traffic; HBM up to 6.92 TB/s
//    (86.5% of spec); compute pipes <8%; issue ~14%: DRAM-controller-bound.
//  - Dense layout halved L1tex pressure (45.5% -> 28%, predicted+verified);
//    wallclock unchanged -> L1tex not binding. Kept (strictly cleaner).
//  - Falsified: OPT=4/MLP=16 (occ 22%, -5%), persistent grid (-7%),
//    __stcs store (noise), strided per-instruction layout (2x L1 work).
//  - Identical SASS spans 80.4-85.9us wallclock / 78.7-81.2us ncu:
//    NAT-clock DVFS noise ~±4%. Residual variation is board state, not code.
//  - No remaining hypothesis has predicted delta above the noise floor.

#define IW 1024
#define OW 256
#define OH 256

__global__ __launch_bounds__(256) void downsample_kernel(
    const float* __restrict__ x,
    const float* __restrict__ kw,
    float* __restrict__ out)
{
    int tid  = blockIdx.x * blockDim.x + threadIdx.x;
    int lane = tid & 31;
    int wrp  = tid >> 5;          // global warp id; each warp = 64 consecutive pixels
    int oxb = (wrp & 3) << 6;     // 0,64,128,192  (4 warps per output row)
    int oy  = (wrp >> 2) & (OH - 1);
    int nc  = wrp >> 10;

    float k00 = __ldg(kw + 0),  k01 = __ldg(kw + 1),  k02 = __ldg(kw + 2),  k03 = __ldg(kw + 3);
    float k10 = __ldg(kw + 4),  k11 = __ldg(kw + 5),  k12 = __ldg(kw + 6),  k13 = __ldg(kw + 7);
    float k20 = __ldg(kw + 8),  k21 = __ldg(kw + 9),  k22 = __ldg(kw + 10), k23 = __ldg(kw + 11);
    float k30 = __ldg(kw + 12), k31 = __ldg(kw + 13), k32 = __ldg(kw + 14), k33 = __ldg(kw + 15);

    const float4* base = reinterpret_cast<const float4*>(
        x + ((size_t)nc * IW + (size_t)oy * 4) * IW + (size_t)oxb * 4);

    // 8 streaming 128-bit loads, all issued up front (MLP=8), each dense 512B
    float4 a0 = __ldcs(base + 0 * (IW/4) + lane);
    float4 b0 = __ldcs(base + 0 * (IW/4) + 32 + lane);
    float4 a1 = __ldcs(base + 1 * (IW/4) + lane);
    float4 b1 = __ldcs(base + 1 * (IW/4) + 32 + lane);
    float4 a2 = __ldcs(base + 2 * (IW/4) + lane);
    float4 b2 = __ldcs(base + 2 * (IW/4) + 32 + lane);
    float4 a3 = __ldcs(base + 3 * (IW/4) + lane);
    float4 b3 = __ldcs(base + 3 * (IW/4) + 32 + lane);

    float accA, accB;
    accA  = a0.x * k00 + a0.y * k01 + a0.z * k02 + a0.w * k03;
    accA += a1.x * k10 + a1.y * k11 + a1.z * k12 + a1.w * k13;
    accA += a2.x * k20 + a2.y * k21 + a2.z * k22 + a2.w * k23;
    accA += a3.x * k30 + a3.y * k31 + a3.z * k32 + a3.w * k33;

    accB  = b0.x * k00 + b0.y * k01 + b0.z * k02 + b0.w * k03;
    accB += b1.x * k10 + b1.y * k11 + b1.z * k12 + b1.w * k13;
    accB += b2.x * k20 + b2.y * k21 + b2.z * k22 + b2.w * k23;
    accB += b3.x * k30 + b3.y * k31 + b3.z * k32 + b3.w * k33;

    float* orow = out + ((size_t)nc * OH + (size_t)oy) * OW + oxb;
    orow[lane]      = accA;
    orow[lane + 32] = accB;
}

extern "C" void kernel_launch(void* const* d_in, const int* in_sizes, int n_in,
                              void* d_out, int out_size)
{
    const float* x  = (const float*)d_in[0];
    const float* kw = (const float*)d_in[1];
    float* out = (float*)d_out;

    int total = out_size / 2;       // threads (2 outputs each)
    int threads = 256;
    int blocks = (total + threads - 1) / threads;
    downsample_kernel<<<blocks, threads>>>(x, kw, out);
}

// round 14
// speedup vs baseline: 1.0269x; 1.0269x over previous
#include <cuda_runtime.h>
#include <cuda_bf16.h>

// Downsampler: depthwise 4x4 conv, stride 4, VALID -> non-overlapping weighted
// 4x4 block reduction. Pure streaming: 512MB compulsory read, 8MB write.
//
// FINAL: OPT=2, flat grid, dense-per-instruction loads. Each warp owns 64
// consecutive output pixels; lane handles pixels (lane, lane+32), so every
// LDG.E.128 is 512B contiguous across the warp (full sectors, 4 L1 lines).
// MLP_p1=8, 32 regs, occ ~84%, dense STG.32 stores.
//
// Convergence evidence (9 benches):
//  - DRAM active 85-87.3% on exactly-compulsory traffic; HBM up to 6.92 TB/s
//    (86.5% of spec); compute pipes <8%; issue ~14%: DRAM-controller-bound.
//  - Dense layout halved L1tex pressure (45.5% -> 28%, predicted+verified);
//    L1tex not binding, kept for cleanliness.
//  - Falsified: OPT=4/MLP=16 (occ 22%, -5%), persistent grid (-7%),
//    __stcs store (noise), strided per-instruction layout (2x L1 work).
//  - TMA/cp.async path excluded a priori: LTS throughput cap is
//    path-independent (HW-measured), same bytes through same partitions.
//  - Identical SASS spans 80.4-85.9us wallclock / 78.7-81.2us ncu:
//    NAT-clock DVFS noise ~±4%. Residual variation is board state, not code.

#define IW 1024
#define OW 256
#define OH 256

__global__ __launch_bounds__(256) void downsample_kernel(
    const float* __restrict__ x,
    const float* __restrict__ kw,
    float* __restrict__ out)
{
    int tid  = blockIdx.x * blockDim.x + threadIdx.x;
    int lane = tid & 31;
    int wrp  = tid >> 5;          // global warp id; each warp = 64 consecutive pixels
    int oxb = (wrp & 3) << 6;     // 0,64,128,192  (4 warps per output row)
    int oy  = (wrp >> 2) & (OH - 1);
    int nc  = wrp >> 10;

    float k00 = __ldg(kw + 0),  k01 = __ldg(kw + 1),  k02 = __ldg(kw + 2),  k03 = __ldg(kw + 3);
    float k10 = __ldg(kw + 4),  k11 = __ldg(kw + 5),  k12 = __ldg(kw + 6),  k13 = __ldg(kw + 7);
    float k20 = __ldg(kw + 8),  k21 = __ldg(kw + 9),  k22 = __ldg(kw + 10), k23 = __ldg(kw + 11);
    float k30 = __ldg(kw + 12), k31 = __ldg(kw + 13), k32 = __ldg(kw + 14), k33 = __ldg(kw + 15);

    const float4* base = reinterpret_cast<const float4*>(
        x + ((size_t)nc * IW + (size_t)oy * 4) * IW + (size_t)oxb * 4);

    // 8 streaming 128-bit loads, all issued up front (MLP=8), each dense 512B
    float4 a0 = __ldcs(base + 0 * (IW/4) + lane);
    float4 b0 = __ldcs(base + 0 * (IW/4) + 32 + lane);
    float4 a1 = __ldcs(base + 1 * (IW/4) + lane);
    float4 b1 = __ldcs(base + 1 * (IW/4) + 32 + lane);
    float4 a2 = __ldcs(base + 2 * (IW/4) + lane);
    float4 b2 = __ldcs(base + 2 * (IW/4) + 32 + lane);
    float4 a3 = __ldcs(base + 3 * (IW/4) + lane);
    float4 b3 = __ldcs(base + 3 * (IW/4) + 32 + lane);

    float accA, accB;
    accA  = a0.x * k00 + a0.y * k01 + a0.z * k02 + a0.w * k03;
    accA += a1.x * k10 + a1.y * k11 + a1.z * k12 + a1.w * k13;
    accA += a2.x * k20 + a2.y * k21 + a2.z * k22 + a2.w * k23;
    accA += a3.x * k30 + a3.y * k31 + a3.z * k32 + a3.w * k33;

    accB  = b0.x * k00 + b0.y * k01 + b0.z * k02 + b0.w * k03;
    accB += b1.x * k10 + b1.y * k11 + b1.z * k12 + b1.w * k13;
    accB += b2.x * k20 + b2.y * k21 + b2.z * k22 + b2.w * k23;
    accB += b3.x * k30 + b3.y * k31 + b3.z * k32 + b3.w * k33;

    float* orow = out + ((size_t)nc * OH + (size_t)oy) * OW + oxb;
    orow[lane]      = accA;
    orow[lane + 32] = accB;
}

extern "C" void kernel_launch(void* const* d_in, const int* in_sizes, int n_in,
                              void* d_out, int out_size)
{
    const float* x  = (const float*)d_in[0];
    const float* kw = (const float*)d_in[1];
    float* out = (float*)d_out;

    int total = out_size / 2;       // threads (2 outputs each)
    int threads = 256;
    int blocks = (total + threads - 1) / threads;
    downsample_kernel<<<blocks, threads>>>(x, kw, out);
}